// round 15
// baseline (speedup 1.0000x reference)
#include <cuda_runtime.h>
#include <math.h>

#define Bz 8
#define Tz 512
#define Dz 128
#define Hz 128
#define BT (Bz*Tz)          // 4096
#define BTH (BT*Hz)         // 524288
#define Lz 2
#define Sc 16               // chunk size
#define NC (Tz/Sc)          // 32 chunks

// ---- scratch (device globals; no allocation allowed) ----
__device__ __align__(128) float gq[BTH];
__device__ __align__(128) float gk[BTH];     // pre-scaled by 1/sqrt(H)
__device__ __align__(128) float gv[BTH];
__device__ __align__(128) float gi[BTH];     // exp(zi)
__device__ __align__(128) float gf[BTH];     // sigmoid(zf)
__device__ __align__(128) float go[BTH];     // sigmoid(zo)
__device__ __align__(128) float gh1[BTH];    // layer-1 output
// chunked-scan scratch
__device__ __align__(128) float gA[BTH];       // Ahat[s][i] = i*v / Pn[s]
__device__ __align__(128) float gAk[BTH];      // ikhat[s][i] = i*k / Pn[s]
__device__ __align__(128) float gPprev[BTH];   // Pn[t-1] (t=0 slot = 1/sqrt(Ptot))
__device__ __align__(128) float gsqP[Bz*NC*Hz];  // sqrt(Ptot)
__device__ __align__(128) float gPtot[Bz*NC*Hz]; // Ptot
__device__ __align__(128) float gnS[Bz*NC*Hz];   // sqrtP * sum_s ikhat[s]
__device__ __align__(128) float gNst[Bz*NC*Hz];  // chunk-start n
__device__ __align__(128) float gS[Bz*NC*Hz*Hz]; // chunk sums -> (in-place) chunk-start C

struct GemmArgs {
  const float* X;
  const float* W[6];
  const float* bias[6];
  int use_h1;
};

// ---- f32x2 packed helpers (sm_103a FFMA2 path; only reachable via PTX) ----
__device__ __forceinline__ unsigned long long dup2(float x) {
  unsigned long long r;
  asm("mov.b64 %0, {%1, %1};" : "=l"(r) : "r"(__float_as_int(x)));
  return r;
}
__device__ __forceinline__ unsigned long long pack2(float lo, float hi) {
  unsigned long long r;
  asm("mov.b64 %0, {%1, %2};" : "=l"(r) : "r"(__float_as_int(lo)), "r"(__float_as_int(hi)));
  return r;
}
__device__ __forceinline__ unsigned long long fma2(unsigned long long a,
                                                   unsigned long long b,
                                                   unsigned long long c) {
  unsigned long long d;
  asm("fma.rn.f32x2 %0, %1, %2, %3;" : "=l"(d) : "l"(a), "l"(b), "l"(c));
  return d;
}
__device__ __forceinline__ void unpack2(unsigned long long p, float& lo, float& hi) {
  int a, b;
  asm("mov.b64 {%0, %1}, %2;" : "=r"(a), "=r"(b) : "l"(p));
  lo = __int_as_float(a);
  hi = __int_as_float(b);
}

// ---------------------------------------------------------------------------
// Kernel 1: fused 6-way projection GEMM + activations, FFMA2 inner loop.
// 128(n) x 128(m) tile, 256 threads, 8x8 microtile, grid (32, 6).
// ---------------------------------------------------------------------------
#define SA 34    // As2 row stride in 8B units
#define SB 130   // Bs row stride in floats
__global__ __launch_bounds__(256) void gemm_act(GemmArgs a) {
  __shared__ __align__(16) unsigned long long As2[128 * SA];
  __shared__ __align__(16) float Bs[32 * SB];
  const float* Xp = a.use_h1 ? gh1 : a.X;

  int tid = threadIdx.x;
  int n0 = blockIdx.x * 128;
  int p = blockIdx.y;
  const float* Wp = a.W[p];

  int tx = tid & 15, ty = tid >> 4;
  int sn = tid >> 3, sk4 = tid & 7;

  unsigned long long acc[8][4];
#pragma unroll
  for (int i = 0; i < 8; i++)
#pragma unroll
    for (int j = 0; j < 4; j++) acc[i][j] = 0ULL;

  float4 xr[4], wr[4];
#pragma unroll
  for (int s = 0; s < 4; s++) {
    int n = sn + s * 32;
    xr[s] = *(const float4*)(Xp + (n0 + n) * Dz + 4 * sk4);
    wr[s] = *(const float4*)(Wp + n * Dz + 4 * sk4);
  }

  for (int it = 0; it < 4; it++) {
#pragma unroll
    for (int s = 0; s < 4; s++) {
      int n = sn + s * 32;
      unsigned long long* arow = &As2[n * SA + 4 * sk4];
      arow[0] = dup2(xr[s].x);
      arow[1] = dup2(xr[s].y);
      arow[2] = dup2(xr[s].z);
      arow[3] = dup2(xr[s].w);
      Bs[(4 * sk4 + 0) * SB + n] = wr[s].x;
      Bs[(4 * sk4 + 1) * SB + n] = wr[s].y;
      Bs[(4 * sk4 + 2) * SB + n] = wr[s].z;
      Bs[(4 * sk4 + 3) * SB + n] = wr[s].w;
    }
    __syncthreads();
    if (it < 3) {
      int kk = (it + 1) * 32;
#pragma unroll
      for (int s = 0; s < 4; s++) {
        int n = sn + s * 32;
        xr[s] = *(const float4*)(Xp + (n0 + n) * Dz + kk + 4 * sk4);
        wr[s] = *(const float4*)(Wp + n * Dz + kk + 4 * sk4);
      }
    }
#pragma unroll 4
    for (int k = 0; k < 32; k += 2) {
      unsigned long long a0[8], a1[8];
#pragma unroll
      for (int i = 0; i < 8; i++) {
        ulonglong2 av = *(const ulonglong2*)&As2[(ty * 8 + i) * SA + k];
        a0[i] = av.x;
        a1[i] = av.y;
      }
      unsigned long long bv0[4], bv1[4];
#pragma unroll
      for (int jp = 0; jp < 4; jp++) {
        bv0[jp] = *(const unsigned long long*)&Bs[k * SB + 32 * jp + 2 * tx];
        bv1[jp] = *(const unsigned long long*)&Bs[(k + 1) * SB + 32 * jp + 2 * tx];
      }
#pragma unroll
      for (int i = 0; i < 8; i++)
#pragma unroll
        for (int jp = 0; jp < 4; jp++)
          acc[i][jp] = fma2(a0[i], bv0[jp], acc[i][jp]);
#pragma unroll
      for (int i = 0; i < 8; i++)
#pragma unroll
        for (int jp = 0; jp < 4; jp++)
          acc[i][jp] = fma2(a1[i], bv1[jp], acc[i][jp]);
    }
    __syncthreads();
  }

  float* outs;
  switch (p) {
    case 0: outs = gq; break;
    case 1: outs = gk; break;
    case 2: outs = gv; break;
    case 3: outs = gi; break;
    case 4: outs = gf; break;
    default: outs = go; break;
  }
  const float kscale = 0.08838834764831845f;  // 1/sqrt(128)
  const float* bp = a.bias[p];
#pragma unroll
  for (int i = 0; i < 8; i++) {
    int n = n0 + ty * 8 + i;
#pragma unroll
    for (int jp = 0; jp < 4; jp++) {
      int m = 32 * jp + 2 * tx;
      float lo, hi;
      unpack2(acc[i][jp], lo, hi);
      float2 bb = *(const float2*)&bp[m];
      float v0 = lo + bb.x, v1 = hi + bb.y;
      float r0, r1;
      if (p == 0)      { r0 = v0; r1 = v1; }
      else if (p == 1) { r0 = v0 * kscale; r1 = v1 * kscale; }
      else if (p == 2) { r0 = v0; r1 = v1; }
      else if (p == 3) { r0 = __expf(v0); r1 = __expf(v1); }
      else             { r0 = __fdividef(1.f, 1.f + __expf(-v0));
                         r1 = __fdividef(1.f, 1.f + __expf(-v1)); }
      *(float2*)&outs[n * Hz + m] = make_float2(r0, r1);
    }
  }
}

// ---------------------------------------------------------------------------
// Kernel 2: fused per-chunk cumsum + local state sums (+ n chunk-sums).
// Phase B FFMA2-packed over j pairs.
// ---------------------------------------------------------------------------
__global__ __launch_bounds__(128) void cumsum_k() {
  __shared__ __align__(16) float ksm[Sc][128];
  int bc = blockIdx.x;
  int i = threadIdx.x;
  int base = bc * Sc * Hz + i;

  float lf[Sc];
  float ct = 0.f;
#pragma unroll
  for (int t = 0; t < Sc; t++) {
    float f = gf[base + t * Hz];
    float l = __logf(f);
    lf[t] = l;
    ct += l;
  }
  float sq2 = 0.5f * ct;

  gPprev[base] = __expf(-sq2);   // t=0 slot: Pn[-1] = 1/sqrt(Ptot)
  float Areg[Sc];
  float c_run = 0.f;
  float sAk = 0.f;
#pragma unroll
  for (int t = 0; t < Sc; t++) {
    c_run += lf[t];
    float e = __expf(sq2 - c_run);
    float ii = gi[base + t * Hz];
    float kk = gk[base + t * Hz];
    float av = ii * gv[base + t * Hz] * e;
    float akv = ii * kk * e;
    Areg[t] = av;
    gA[base + t * Hz]  = av;
    gAk[base + t * Hz] = akv;
    sAk += akv;
    ksm[t][i] = kk;
    if (t < Sc - 1) gPprev[base + (t + 1) * Hz] = __expf(c_run - sq2);
  }
  float sp = __expf(sq2);
  gsqP[bc * Hz + i]  = sp;
  gPtot[bc * Hz + i] = __expf(ct);
  gnS[bc * Hz + i]   = sp * sAk;
  unsigned long long Ap[Sc];
#pragma unroll
  for (int t = 0; t < Sc; t++) Ap[t] = dup2(Areg[t]);
  __syncthreads();

  // Phase B: packed j-pairs; ksm fetched as 16B (2 ull) per s.
  long ob = (long)bc * Hz * Hz + i;
#pragma unroll 4
  for (int j0 = 0; j0 < Hz; j0 += 4) {
    unsigned long long a01 = 0ULL, a23 = 0ULL;
#pragma unroll
    for (int s = 0; s < Sc; s++) {
      ulonglong2 kv = *(const ulonglong2*)&ksm[s][j0];
      a01 = fma2(Ap[s], kv.x, a01);
      a23 = fma2(Ap[s], kv.y, a23);
    }
    float l0, h0, l1, h1;
    unpack2(a01, l0, h0);
    unpack2(a23, l1, h1);
    gS[ob + (long)(j0 + 0) * Hz] = sp * l0;
    gS[ob + (long)(j0 + 1) * Hz] = sp * h0;
    gS[ob + (long)(j0 + 2) * Hz] = sp * l1;
    gS[ob + (long)(j0 + 3) * Hz] = sp * h1;
  }
}

// ---------------------------------------------------------------------------
// Kernel 3: streaming chunk-state scan, IN-PLACE (gS -> chunk-start C),
// with the scalar n-scan folded in as the last Bz blocks.
// ---------------------------------------------------------------------------
__global__ __launch_bounds__(128) void combine_k() {
  int blk = blockIdx.x;
  int i = threadIdx.x;
  if (blk < Bz * Hz) {
    int b = blk >> 7;
    int j = blk & 127;
    long base = ((long)b * NC * Hz + j) * Hz + i;
    int pbase = b * NC * Hz + i;
    const long CS = (long)Hz * Hz;

    float C = 0.f;
    float s_next = gS[base];
#pragma unroll 4
    for (int c = 0; c < NC; c++) {
      float s = s_next;
      if (c + 1 < NC) s_next = gS[base + (long)(c + 1) * CS];
      float pt = gPtot[pbase + c * Hz];
      gS[base + (long)c * CS] = C;
      C = fmaf(pt, C, s);
    }
  } else {
    int b = blk - Bz * Hz;
    float n = 0.f;
#pragma unroll 4
    for (int c = 0; c < NC; c++) {
      int o = (b * NC + c) * Hz + i;
      gNst[o] = n;
      n = fmaf(gPtot[o], n, gnS[o]);
    }
  }
}

// ---------------------------------------------------------------------------
// Kernel 4: per-chunk outputs + fused denominator. 256 THREADS (fix):
// thread = (i = tid&127, half = tid>>7); each half owns 8 timesteps.
// ---------------------------------------------------------------------------
__global__ __launch_bounds__(256) void out_k(float* dout, int last) {
  __shared__ __align__(16) float qsm[Sc][132];
  __shared__ __align__(16) float ksm[Sc][132];
  __shared__ float Asm[Sc][128];
  __shared__ float dsm[Sc][128];
  __shared__ __align__(16) float Gs[Sc][Sc];
  __shared__ float den_s[Sc];

  int bc = blockIdx.x;
  int tid = threadIdx.x;
  int i = tid & 127;
  int half = tid >> 7;
  int row0 = bc * Sc * Hz;
  float* outp = last ? dout : gh1;

  if (half == 0) {
    // stage q + denominator partials (serial run over all 16 t)
    float run = gsqP[bc * Hz + i] * gNst[bc * Hz + i];
#pragma unroll
    for (int t = 0; t < Sc; t++) {
      int idx = row0 + t * Hz + i;
      float qv = gq[idx];
      qsm[t][i] = qv;
      dsm[t][i] = gPprev[idx] * run * qv;
      run += gAk[idx];
    }
  } else {
    // stage k + Ahat
#pragma unroll
    for (int t = 0; t < Sc; t++) {
      int idx = row0 + t * Hz + i;
      ksm[t][i] = gk[idx];
      Asm[t][i] = gA[idx];
    }
  }
  __syncthreads();

  // G[t][s] = k_s . q_t (strict lower; zero elsewhere). One entry per thread.
  {
    int t = tid >> 4, s = tid & 15;
    float gacc = 0.f;
    if (s < t) {
      unsigned long long g2 = 0ULL;
#pragma unroll 8
      for (int d = 0; d < Hz; d += 4) {
        ulonglong2 kk = *(const ulonglong2*)&ksm[s][d];
        ulonglong2 qq = *(const ulonglong2*)&qsm[t][d];
        g2 = fma2(kk.x, qq.x, g2);
        g2 = fma2(kk.y, qq.y, g2);
      }
      float lo, hi;
      unpack2(g2, lo, hi);
      gacc = lo + hi;
    }
    Gs[t][s] = gacc;
  }

  // den reduction: 8 warps, 2 timesteps each
  {
    int w = tid >> 5, lane = tid & 31;
#pragma unroll
    for (int tt = 0; tt < 2; tt++) {
      int t = w * 2 + tt;
      float s = dsm[t][lane] + dsm[t][lane + 32] + dsm[t][lane + 64] + dsm[t][lane + 96];
#pragma unroll
      for (int o = 16; o; o >>= 1) s += __shfl_xor_sync(0xffffffffu, s, o);
      if (lane == 0) den_s[t] = fmaxf(fabsf(s), 1.f);
    }
  }
  __syncthreads();

  int t0 = half * 8;
  unsigned long long acc2[8];
#pragma unroll
  for (int tt = 0; tt < 8; tt++) acc2[tt] = 0ULL;

  // inter: acc[t] += Cstart[i][j] * q_t[j]; packed j-pairs, q via LDS.128
  const float* cbase = gS + (long)bc * Hz * Hz + i;
  for (int j0 = 0; j0 < Hz; j0 += 16) {
    unsigned long long cp[8];
#pragma unroll
    for (int m = 0; m < 8; m++) {
      float lo = cbase[(long)(j0 + 2 * m) * Hz];
      float hi = cbase[(long)(j0 + 2 * m + 1) * Hz];
      cp[m] = pack2(lo, hi);
    }
#pragma unroll
    for (int tt = 0; tt < 8; tt++) {
#pragma unroll
      for (int m4 = 0; m4 < 4; m4++) {
        ulonglong2 qq = *(const ulonglong2*)&qsm[t0 + tt][j0 + 4 * m4];
        acc2[tt] = fma2(cp[2 * m4 + 0], qq.x, acc2[tt]);
        acc2[tt] = fma2(cp[2 * m4 + 1], qq.y, acc2[tt]);
      }
    }
  }
  float sp = gsqP[bc * Hz + i];
  float acc[8];
#pragma unroll
  for (int tt = 0; tt < 8; tt++) {
    float lo, hi;
    unpack2(acc2[tt], lo, hi);
    acc[tt] = sp * (lo + hi);
  }

  // intra: acc[t] += sum_s G[t][s] * Ahat[s][i]
#pragma unroll
  for (int s4 = 0; s4 < 4; s4++) {
    float a0 = Asm[4 * s4 + 0][i];
    float a1 = Asm[4 * s4 + 1][i];
    float a2 = Asm[4 * s4 + 2][i];
    float a3 = Asm[4 * s4 + 3][i];
#pragma unroll
    for (int tt = 0; tt < 8; tt++) {
      float4 g = *(const float4*)&Gs[t0 + tt][4 * s4];
      acc[tt] = fmaf(g.x, a0, acc[tt]);
      acc[tt] = fmaf(g.y, a1, acc[tt]);
      acc[tt] = fmaf(g.z, a2, acc[tt]);
      acc[tt] = fmaf(g.w, a3, acc[tt]);
    }
  }

  // epilogue
#pragma unroll
  for (int tt = 0; tt < 8; tt++) {
    int t = t0 + tt;
    int idx = row0 + t * Hz + i;
    float ht = gPprev[idx] * acc[tt];
    outp[idx] = go[idx] * __fdividef(ht, den_s[t]);
  }
}

// ---------------------------------------------------------------------------
// Host launch: 4 kernels per layer, single stream.
// ---------------------------------------------------------------------------
extern "C" void kernel_launch(void* const* d_in, const int* in_sizes, int n_in,
                              void* d_out, int out_size) {
  const float* x = (const float*)d_in[0];
  const float* W[6];
  const float* Bb[6];

  if (n_in >= 13 && in_sizes[2] == Lz * Hz) {
    for (int j = 0; j < 6; j++) {
      W[j]  = (const float*)d_in[1 + 2 * j];
      Bb[j] = (const float*)d_in[2 + 2 * j];
    }
  } else {
    for (int j = 0; j < 6; j++) {
      W[j]  = (const float*)d_in[1 + j];
      Bb[j] = (const float*)d_in[7 + j];
    }
  }

  for (int l = 0; l < Lz; l++) {
    GemmArgs a;
    a.X = x;
    a.use_h1 = l;
    for (int j = 0; j < 6; j++) {
      a.W[j]    = W[j]  + l * Hz * Dz;
      a.bias[j] = Bb[j] + l * Hz;
    }
    gemm_act<<<dim3(BT / 128, 6), 256>>>(a);
    cumsum_k<<<Bz * NC, 128>>>();
    combine_k<<<Bz * Hz + Bz, 128>>>();
    out_k<<<Bz * NC, 256>>>((float*)d_out, (l == Lz - 1) ? 1 : 0);   // FIX: 256 threads
  }
}